// round 10
// baseline (speedup 1.0000x reference)
#include <cuda_runtime.h>

#define BATCH 4096
#define FEAT  512
#define NUMC  10000

#define BLOCK_THREADS 1024
#define WARPS_PER_BLOCK (BLOCK_THREADS / 32)        // 32
#define GRID_BLOCKS (BATCH / WARPS_PER_BLOCK)       // 128

#define FIX_SCALE 67108864.0                        // 2^26 (Q.26 fixed point)
#define CNT_SHIFT 53
#define SUM_MASK  ((1ULL << CNT_SHIFT) - 1ULL)

// Scratch (no cudaMalloc allowed). Zero-init; reset by the last block each run.
// bits [0,53)  = Q.26 fixed-point sum (max ~2^48; integer adds commutative)
// bits [53,64) = completed-block counter (128 * 2^53 = 2^60 < 2^64)
__device__ unsigned long long g_isum;

__global__ void __launch_bounds__(BLOCK_THREADS)
center_loss_kernel(const float* __restrict__ x,
                   const int*   __restrict__ labels32,
                   const float* __restrict__ centers,
                   float*       __restrict__ out) {
    const int lane = threadIdx.x & 31;
    const int wid  = threadIdx.x >> 5;
    const int row  = blockIdx.x * WARPS_PER_BLOCK + wid;

    // dtype probe: odd words of first 64 int32 all zero <=> int64 labels.
    // P(false positive for int32 labels) = 1e-128. Fixed probe, every warp
    // (L1/L2-resident after the first warp touches it).
    int probe = __ldg(&labels32[2 * lane + 1]);
    int labA  = __ldg(&labels32[2 * row]);    // int64 candidate (low word)
    int labB  = __ldg(&labels32[row]);        // int32 candidate

    const float4* xr = reinterpret_cast<const float4*>(x + (size_t)row * FEAT);
    float4 xv[4];
#pragma unroll
    for (int i = 0; i < 4; i++) xv[i] = __ldg(&xr[lane + 32 * i]);

    bool is64 = (__ballot_sync(0xffffffffu, probe != 0) == 0u);
    int  lab  = is64 ? labA : labB;

    const float4* cr = reinterpret_cast<const float4*>(centers + (size_t)lab * FEAT);

    float a0 = 0.f, a1 = 0.f, a2 = 0.f, a3 = 0.f;
#pragma unroll
    for (int i = 0; i < 4; i++) {
        float4 cv = __ldg(&cr[lane + 32 * i]);
        float d0 = xv[i].x - cv.x;
        float d1 = xv[i].y - cv.y;
        float d2 = xv[i].z - cv.z;
        float d3 = xv[i].w - cv.w;
        a0 = fmaf(d0, d0, a0);
        a1 = fmaf(d1, d1, a1);
        a2 = fmaf(d2, d2, a2);
        a3 = fmaf(d3, d3, a3);
    }
    float acc = (a0 + a1) + (a2 + a3);
#pragma unroll
    for (int o = 16; o > 0; o >>= 1)
        acc += __shfl_xor_sync(0xffffffffu, acc, o);

    __shared__ float sh[WARPS_PER_BLOCK];
    if (lane == 0)
        sh[wid] = fminf(fmaxf(acc, 1e-12f), 1e12f);   // clip diagonal entry
    __syncthreads();

    // warp 0 reduces the 32 per-warp sums with a deterministic shuffle tree
    if (wid == 0) {
        float bs = sh[lane];
#pragma unroll
        for (int o = 16; o > 0; o >>= 1)
            bs += __shfl_xor_sync(0xffffffffu, bs, o);

        if (lane == 0) {
            // ONE atomic: accumulate Q.26 sum AND bump the block counter.
            unsigned long long q =
                (unsigned long long)__double2ll_rn((double)bs * FIX_SCALE);
            unsigned long long old =
                atomicAdd(&g_isum, q + (1ULL << CNT_SHIFT));

            if ((old >> CNT_SHIFT) == (unsigned long long)(GRID_BLOCKS - 1)) {
                // Final arrival: grand total already in hand — no read-back.
                unsigned long long tot = (old & SUM_MASK) + q;
                double t = (double)tot * (1.0 / FIX_SCALE);
                out[0] = (float)(t / (double)BATCH + (double)(NUMC - 1) * 1e-12);
                g_isum = 0ULL;   // replay-safe reset (all contributions landed)
            }
        }
    }
}

extern "C" void kernel_launch(void* const* d_in, const int* in_sizes, int n_in,
                              void* d_out, int out_size) {
    const float* x       = (const float*)d_in[0];
    const int*   labels  = (const int*)  d_in[1];
    const float* centers = (const float*)d_in[2];
    float*       out     = (float*)d_out;

    center_loss_kernel<<<GRID_BLOCKS, BLOCK_THREADS>>>(x, labels, centers, out);
}

// round 11
// speedup vs baseline: 1.0081x; 1.0081x over previous
#include <cuda_runtime.h>

#define BATCH 4096
#define FEAT  512
#define NUMC  10000

#define BLOCK_THREADS 256
#define WARPS_PER_BLOCK (BLOCK_THREADS / 32)        // 8
#define GRID_BLOCKS (BATCH / WARPS_PER_BLOCK)       // 512

#define FIX_SCALE 67108864.0                        // 2^26 (Q.26 fixed point)
#define CNT_SHIFT 53
#define SUM_MASK  ((1ULL << CNT_SHIFT) - 1ULL)

// Scratch (no cudaMalloc allowed). Zero-init; reset by the last block each run.
// bits [0,53)  = Q.26 fixed-point sum (max ~2^48; integer adds commutative)
// bits [53,64) = completed-block counter (512 * 2^53 = 2^62 < 2^64)
__device__ unsigned long long g_isum;

__global__ void __launch_bounds__(BLOCK_THREADS)
center_loss_kernel(const float* __restrict__ x,
                   const int*   __restrict__ labels32,
                   const float* __restrict__ centers,
                   float*       __restrict__ out) {
    const int lane = threadIdx.x & 31;
    const int wid  = threadIdx.x >> 5;
    const int row  = blockIdx.x * WARPS_PER_BLOCK + wid;

    // ---- label loads: one int2 covers both interpretations ------------------
    // int64 view: labPair.x = low word (the label), labPair.y = high word (0).
    // int32 view: labels32[row] is the label.
    // dtype probe: odd words of the first 64 int32 are all zero <=> int64.
    // P(false positive for int32 labels) = 1e-128. Fixed probe, every warp.
    int  probe   = __ldg(&labels32[2 * lane + 1]);
    int2 labPair = __ldg(reinterpret_cast<const int2*>(labels32) + row); // {2*row, 2*row+1}
    int  labB    = __ldg(&labels32[row]);   // int32 candidate

    const float4* xr = reinterpret_cast<const float4*>(x + (size_t)row * FEAT);
    float4 xv[4];
#pragma unroll
    for (int i = 0; i < 4; i++) xv[i] = __ldg(&xr[lane + 32 * i]);

    bool is64 = (__ballot_sync(0xffffffffu, probe != 0) == 0u);
    int  lab  = is64 ? labPair.x : labB;

    const float4* cr = reinterpret_cast<const float4*>(centers + (size_t)lab * FEAT);

    float a0 = 0.f, a1 = 0.f, a2 = 0.f, a3 = 0.f;
#pragma unroll
    for (int i = 0; i < 4; i++) {
        float4 cv = __ldg(&cr[lane + 32 * i]);
        float d0 = xv[i].x - cv.x;
        float d1 = xv[i].y - cv.y;
        float d2 = xv[i].z - cv.z;
        float d3 = xv[i].w - cv.w;
        a0 = fmaf(d0, d0, a0);
        a1 = fmaf(d1, d1, a1);
        a2 = fmaf(d2, d2, a2);
        a3 = fmaf(d3, d3, a3);
    }
    float acc = (a0 + a1) + (a2 + a3);
#pragma unroll
    for (int o = 16; o > 0; o >>= 1)
        acc += __shfl_xor_sync(0xffffffffu, acc, o);

    __shared__ float sh[WARPS_PER_BLOCK];
    if (lane == 0)
        sh[wid] = fminf(fmaxf(acc, 1e-12f), 1e12f);   // clip diagonal entry
    __syncthreads();

    // warp 0: shuffle-tree over the 8 per-warp sums (fixed order, deterministic)
    if (wid == 0) {
        float bs = (lane < WARPS_PER_BLOCK) ? sh[lane] : 0.0f;
#pragma unroll
        for (int o = 4; o > 0; o >>= 1)
            bs += __shfl_xor_sync(0xffffffffu, bs, o);

        if (lane == 0) {
            // ONE atomic: accumulate Q.26 sum AND bump the block counter.
            unsigned long long q =
                (unsigned long long)__double2ll_rn((double)bs * FIX_SCALE);
            unsigned long long old =
                atomicAdd(&g_isum, q + (1ULL << CNT_SHIFT));

            if ((old >> CNT_SHIFT) == (unsigned long long)(GRID_BLOCKS - 1)) {
                // Final arrival: grand total already in hand — no read-back.
                unsigned long long tot = (old & SUM_MASK) + q;
                double t = (double)tot * (1.0 / FIX_SCALE);
                out[0] = (float)(t / (double)BATCH + (double)(NUMC - 1) * 1e-12);
                g_isum = 0ULL;   // replay-safe reset (all contributions landed)
            }
        }
    }
}

extern "C" void kernel_launch(void* const* d_in, const int* in_sizes, int n_in,
                              void* d_out, int out_size) {
    const float* x       = (const float*)d_in[0];
    const int*   labels  = (const int*)  d_in[1];
    const float* centers = (const float*)d_in[2];
    float*       out     = (float*)d_out;

    center_loss_kernel<<<GRID_BLOCKS, BLOCK_THREADS>>>(x, labels, centers, out);
}

// round 12
// speedup vs baseline: 1.0122x; 1.0041x over previous
#include <cuda_runtime.h>

#define BATCH 4096
#define FEAT  512
#define NUMC  10000

#define BLOCK_THREADS 256
#define WARPS_PER_BLOCK (BLOCK_THREADS / 32)        // 8
#define ROWS_PER_WARP 2
#define ROWS_PER_BLOCK (WARPS_PER_BLOCK * ROWS_PER_WARP)   // 16
#define GRID_BLOCKS (BATCH / ROWS_PER_BLOCK)               // 256

#define FIX_SCALE 67108864.0                        // 2^26 (Q.26 fixed point)
#define CNT_SHIFT 53
#define SUM_MASK  ((1ULL << CNT_SHIFT) - 1ULL)

// Scratch (no cudaMalloc allowed). Zero-init; reset by the last block each run.
// bits [0,53)  = Q.26 fixed-point sum (max ~2^48; integer adds commutative)
// bits [53,64) = completed-block counter (256 * 2^53 = 2^61 < 2^64)
__device__ unsigned long long g_isum;

__global__ void __launch_bounds__(BLOCK_THREADS)
center_loss_kernel(const float* __restrict__ x,
                   const int*   __restrict__ labels32,
                   const float* __restrict__ centers,
                   float*       __restrict__ out) {
    const int lane = threadIdx.x & 31;
    const int wid  = threadIdx.x >> 5;
    const int row0 = blockIdx.x * ROWS_PER_BLOCK + wid * ROWS_PER_WARP;
    const int row1 = row0 + 1;

    // ---- epoch 1: ALL independent loads for BOTH rows, issued up front ------
    // dtype probe: odd words of first 64 int32 all zero <=> int64 labels.
    // P(false positive for int32 labels) = 1e-128. Fixed probe, every warp.
    int probe  = __ldg(&labels32[2 * lane + 1]);
    int labA0  = __ldg(&labels32[2 * row0]);   // int64 candidates (low words)
    int labA1  = __ldg(&labels32[2 * row1]);
    int labB0  = __ldg(&labels32[row0]);       // int32 candidates
    int labB1  = __ldg(&labels32[row1]);

    const float4* xr0 = reinterpret_cast<const float4*>(x + (size_t)row0 * FEAT);
    const float4* xr1 = reinterpret_cast<const float4*>(x + (size_t)row1 * FEAT);
    float4 xv0[4], xv1[4];
#pragma unroll
    for (int i = 0; i < 4; i++) xv0[i] = __ldg(&xr0[lane + 32 * i]);
#pragma unroll
    for (int i = 0; i < 4; i++) xv1[i] = __ldg(&xr1[lane + 32 * i]);

    bool is64 = (__ballot_sync(0xffffffffu, probe != 0) == 0u);
    int  lab0 = is64 ? labA0 : labB0;
    int  lab1 = is64 ? labA1 : labB1;

    // ---- epoch 2: BOTH center gathers issued back-to-back --------------------
    const float4* cr0 = reinterpret_cast<const float4*>(centers + (size_t)lab0 * FEAT);
    const float4* cr1 = reinterpret_cast<const float4*>(centers + (size_t)lab1 * FEAT);

    float p0 = 0.f, p1 = 0.f, q0 = 0.f, q1 = 0.f;
#pragma unroll
    for (int i = 0; i < 4; i++) {
        float4 cv0 = __ldg(&cr0[lane + 32 * i]);
        float4 cv1 = __ldg(&cr1[lane + 32 * i]);
        float d;
        d = xv0[i].x - cv0.x; p0 = fmaf(d, d, p0);
        d = xv0[i].y - cv0.y; p1 = fmaf(d, d, p1);
        d = xv0[i].z - cv0.z; p0 = fmaf(d, d, p0);
        d = xv0[i].w - cv0.w; p1 = fmaf(d, d, p1);
        d = xv1[i].x - cv1.x; q0 = fmaf(d, d, q0);
        d = xv1[i].y - cv1.y; q1 = fmaf(d, d, q1);
        d = xv1[i].z - cv1.z; q0 = fmaf(d, d, q0);
        d = xv1[i].w - cv1.w; q1 = fmaf(d, d, q1);
    }
    float acc0 = p0 + p1;
    float acc1 = q0 + q1;
#pragma unroll
    for (int o = 16; o > 0; o >>= 1) {
        acc0 += __shfl_xor_sync(0xffffffffu, acc0, o);
        acc1 += __shfl_xor_sync(0xffffffffu, acc1, o);
    }

    __shared__ float sh[WARPS_PER_BLOCK];
    if (lane == 0) {
        // clip each diagonal entry, then pair-sum (deterministic per warp)
        float c0 = fminf(fmaxf(acc0, 1e-12f), 1e12f);
        float c1 = fminf(fmaxf(acc1, 1e-12f), 1e12f);
        sh[wid] = c0 + c1;
    }
    __syncthreads();

    // warp 0: fixed-order shuffle tree over the 8 per-warp sums
    if (wid == 0) {
        float bs = (lane < WARPS_PER_BLOCK) ? sh[lane] : 0.0f;
#pragma unroll
        for (int o = 4; o > 0; o >>= 1)
            bs += __shfl_xor_sync(0xffffffffu, bs, o);

        if (lane == 0) {
            // ONE atomic: accumulate Q.26 sum AND bump the block counter.
            unsigned long long q =
                (unsigned long long)__double2ll_rn((double)bs * FIX_SCALE);
            unsigned long long old =
                atomicAdd(&g_isum, q + (1ULL << CNT_SHIFT));

            if ((old >> CNT_SHIFT) == (unsigned long long)(GRID_BLOCKS - 1)) {
                // Final arrival: grand total already in hand — no read-back.
                unsigned long long tot = (old & SUM_MASK) + q;
                double t = (double)tot * (1.0 / FIX_SCALE);
                out[0] = (float)(t / (double)BATCH + (double)(NUMC - 1) * 1e-12);
                g_isum = 0ULL;   // replay-safe reset (all contributions landed)
            }
        }
    }
}

extern "C" void kernel_launch(void* const* d_in, const int* in_sizes, int n_in,
                              void* d_out, int out_size) {
    const float* x       = (const float*)d_in[0];
    const int*   labels  = (const int*)  d_in[1];
    const float* centers = (const float*)d_in[2];
    float*       out     = (float*)d_out;

    center_loss_kernel<<<GRID_BLOCKS, BLOCK_THREADS>>>(x, labels, centers, out);
}